// round 11
// baseline (speedup 1.0000x reference)
#include <cuda_runtime.h>
#include <cstdint>

// Problem constants
#define BB   4096
#define TT   2048
#define HH   128
#define BR   14            // batch rows per CTA (296 x 14 = 4144 >= 4096, tail padded)
#define NCTA 296           // exactly 2 CTAs per SM — cross-CTA barrier overlap
#define NTHR 128           // 1 warp per SMSP per CTA; 2 independent warps/SMSP on the SM
#define NOUT 8
#define NRP  7             // row pairs per thread (14 rows)
#define HSTR 20            // smem row stride (floats): 80B, 16B-aligned (LDS.128-safe)

typedef unsigned long long ull;

// ---------- packed fp32x2 helpers ----------
__device__ __forceinline__ ull pack2(float a, float b) {
    ull r; asm("mov.b64 %0,{%1,%2};" : "=l"(r) : "f"(a), "f"(b)); return r;
}
__device__ __forceinline__ void unpack2(ull p, float& a, float& b) {
    asm("mov.b64 {%0,%1},%2;" : "=f"(a), "=f"(b) : "l"(p));
}
__device__ __forceinline__ ull fma2(ull a, ull b, ull c) {
    ull d; asm("fma.rn.f32x2 %0,%1,%2,%3;" : "=l"(d) : "l"(a), "l"(b), "l"(c)); return d;
}

// ---------- HW tanh activations (MUFU.TANH) ----------
__device__ __forceinline__ float tanha(float x) {
    float r; asm("tanh.approx.f32 %0,%1;" : "=f"(r) : "f"(x)); return r;
}
__device__ __forceinline__ float sigf(float x) {
    return fmaf(0.5f, tanha(0.5f * x), 0.5f);
}

// Transposed weights: [mat][k*128 + j] = float4 (g0,g1,g2,g3) for unit j, col k.
__device__ float4 g_wt[3][HH * HH];

__global__ void prep_w_kernel(const float* __restrict__ whh1,
                              const float* __restrict__ wih2,
                              const float* __restrict__ whh2)
{
    const int idx = blockIdx.x * blockDim.x + threadIdx.x;
    if (idx >= HH * HH) return;
    const int k = idx >> 7, j = idx & 127;
    const float* Ws[3] = { whh1, wih2, whh2 };
    #pragma unroll
    for (int m = 0; m < 3; ++m) {
        const float* W = Ws[m];
        g_wt[m][idx] = make_float4(W[(0 * HH + j) * HH + k],
                                   W[(1 * HH + j) * HH + k],
                                   W[(2 * HH + j) * HH + k],
                                   W[(3 * HH + j) * HH + k]);
    }
}

// One k4-group of the 14x512x128 GEMM slice: 3 row quads + 1 tail pair per thread.
__device__ __forceinline__ void gemm_k4(ull (&acc)[4][NRP],
                                        const float4* __restrict__ wt,
                                        const float* __restrict__ hbuf,
                                        int k4, float4 (&wv)[4])
{
    float4 wn[4];
    const int kb = (k4 < 31) ? (k4 + 1) * 4 : 124;
    #pragma unroll
    for (int i = 0; i < 4; ++i) wn[i] = __ldg(wt + (kb + i) * HH);
    const float* hk = hbuf + (k4 * 4) * HSTR;
    #pragma unroll
    for (int kk = 0; kk < 4; ++kk) {
        const ull wp0 = pack2(wv[kk].x, wv[kk].x);
        const ull wp1 = pack2(wv[kk].y, wv[kk].y);
        const ull wp2 = pack2(wv[kk].z, wv[kk].z);
        const ull wp3 = pack2(wv[kk].w, wv[kk].w);
        const float* hkk = hk + kk * HSTR;
        #pragma unroll
        for (int rq = 0; rq < 3; ++rq) {                 // quads: rows 0..11
            const float4 h4 = *(const float4*)(hkk + 4 * rq);
            const ull hp0 = pack2(h4.x, h4.y);
            const ull hp1 = pack2(h4.z, h4.w);
            const int p = 2 * rq;
            acc[0][p]   = fma2(wp0, hp0, acc[0][p]);
            acc[1][p]   = fma2(wp1, hp0, acc[1][p]);
            acc[2][p]   = fma2(wp2, hp0, acc[2][p]);
            acc[3][p]   = fma2(wp3, hp0, acc[3][p]);
            acc[0][p+1] = fma2(wp0, hp1, acc[0][p+1]);
            acc[1][p+1] = fma2(wp1, hp1, acc[1][p+1]);
            acc[2][p+1] = fma2(wp2, hp1, acc[2][p+1]);
            acc[3][p+1] = fma2(wp3, hp1, acc[3][p+1]);
        }
        {                                                // tail pair: rows 12,13
            const ull hp = *(const ull*)(hkk + 12);
            acc[0][6] = fma2(wp0, hp, acc[0][6]);
            acc[1][6] = fma2(wp1, hp, acc[1][6]);
            acc[2][6] = fma2(wp2, hp, acc[2][6]);
            acc[3][6] = fma2(wp3, hp, acc[3][6]);
        }
    }
    #pragma unroll
    for (int i = 0; i < 4; ++i) wv[i] = wn[i];
}

// One row-pair of activations (gates -> c,h), static pair index P.
#define ACT_PAIR(accX, cX, hdst, P) do {                                     \
    float iv0, iv1, fv0, fv1, gv0, gv1, ov0, ov1;                            \
    unpack2(accX[0][P], iv0, iv1);                                           \
    unpack2(accX[1][P], fv0, fv1);                                           \
    unpack2(accX[2][P], gv0, gv1);                                           \
    unpack2(accX[3][P], ov0, ov1);                                           \
    {   const float cn = sigf(fv0) * cX[2*(P)] + sigf(iv0) * tanha(gv0);     \
        cX[2*(P)] = cn;                                                      \
        (hdst)[2*(P)] = sigf(ov0) * tanha(cn); }                             \
    {   const float cn = sigf(fv1) * cX[2*(P)+1] + sigf(iv1) * tanha(gv1);   \
        cX[2*(P)+1] = cn;                                                    \
        (hdst)[2*(P)+1] = sigf(ov1) * tanha(cn); }                           \
} while (0)

// Dynamic smem layout (floats)
#define SM_H1  0                          // [2][128][HSTR]
#define SM_H2  (SM_H1 + 2 * HH * HSTR)    // [2][128][HSTR]
#define SM_XS  (SM_H2 + 2 * HH * HSTR)    // [64][HSTR]
#define SM_W1  (SM_XS + 64 * HSTR)        // [128][8] transposed [k][oo]
#define SM_W2  (SM_W1 + NOUT * HH)        // [128][8]
#define SM_B1  (SM_W2 + NOUT * HH)        // [8]
#define SM_B2  (SM_B1 + NOUT)             // [8]
#define SM_SB1 (SM_B2 + NOUT)             // [128][8] packed (bb1,bb1) per gate, per j
#define SM_SB2 (SM_SB1 + HH * 8)          // [128][8] packed (bb2,bb2)
#define SM_SWI (SM_SB2 + HH * 8)          // [128][8] packed (wi,wi)
#define SM_TOT (SM_SWI + HH * 8)          // 16656 floats ~= 65.1 KB per CTA

__global__ void __launch_bounds__(NTHR, 2)
lstm_kernel(const float* __restrict__ x,
            const float* __restrict__ wih1,
            const float* __restrict__ bih1, const float* __restrict__ bhh1,
            const float* __restrict__ bih2, const float* __restrict__ bhh2,
            const float* __restrict__ W1, const float* __restrict__ b1,
            const float* __restrict__ W2, const float* __restrict__ b2,
            float* __restrict__ out)
{
    extern __shared__ float sm[];
    float* h1s = sm + SM_H1;
    float* h2s = sm + SM_H2;
    float* xs  = sm + SM_XS;
    float* W1s = sm + SM_W1;
    float* W2s = sm + SM_W2;
    float* b1s = sm + SM_B1;
    float* b2s = sm + SM_B2;
    float* sb1 = sm + SM_SB1;
    float* sb2 = sm + SM_SB2;
    float* swi = sm + SM_SWI;

    const int tid = threadIdx.x;
    const int j   = tid;                 // hidden unit owned by this thread (0..127)
    const int r0  = blockIdx.x * BR;     // first batch row of this CTA

    // ---- init smem ----
    for (int i = tid; i < 2 * HH * HSTR; i += NTHR) { h1s[i] = 0.0f; h2s[i] = 0.0f; }
    for (int i = tid; i < NOUT * HH;     i += NTHR) {
        const int oo = i / HH, k = i % HH;
        W1s[k * NOUT + oo] = W1[i];
        W2s[k * NOUT + oo] = W2[i];
    }
    if (tid < NOUT) { b1s[tid] = b1[tid]; b2s[tid] = b2[tid]; }
    {
        #pragma unroll
        for (int g = 0; g < 4; ++g) {
            const int row = g * HH + tid;
            const float bb1 = bih1[row] + bhh1[row];
            const float bb2 = bih2[row] + bhh2[row];
            const float wv  = wih1[row];           // W_ih1 is (512,1)
            sb1[tid * 8 + 2 * g] = bb1; sb1[tid * 8 + 2 * g + 1] = bb1;
            sb2[tid * 8 + 2 * g] = bb2; sb2[tid * 8 + 2 * g + 1] = bb2;
            swi[tid * 8 + 2 * g] = wv;  swi[tid * 8 + 2 * g + 1] = wv;
        }
    }
    // ---- stage x tile 0 (clamped rows for padded tail CTAs) ----
    for (int idx = tid; idx < BR * 64; idx += NTHR) {
        const int rr = idx / 64, tt2 = idx % 64;
        const int gr = r0 + rr;
        xs[tt2 * HSTR + rr] = x[(size_t)(gr < BB ? gr : BB - 1) * TT + tt2];
    }

    // cell state in registers: c[cell][local row 0..13] for unit j
    float c1r[2 * NRP], c2r[2 * NRP];
    #pragma unroll
    for (int i = 0; i < 2 * NRP; ++i) { c1r[i] = 0.0f; c2r[i] = 0.0f; }

    const float4* wt1 = g_wt[0] + j;   // whh1
    const float4* wt2 = g_wt[1] + j;   // wih2
    const float4* wt3 = g_wt[2] + j;   // whh2
    const ull* b1pj = (const ull*)(sb1 + j * 8);
    const ull* b2pj = (const ull*)(sb2 + j * 8);
    const ull* wipj = (const ull*)(swi + j * 8);

    __syncthreads();

    ull acc1[4][NRP], acc2[4][NRP];
    const int rr_out = tid >> 3;               // 0..15 (rows >= BR inactive)
    const int oo_out = tid & 7;
    const bool wout  = (rr_out < BR) && (r0 + rr_out < BB);
    const size_t OUTS_BASE = (size_t)BB * NOUT;

    // ---- prologue: acc1 = b1 + wi*x(0)  (h1(-1)=0) ----
    {
        const float* xrow = xs;
        #pragma unroll
        for (int rq = 0; rq < 3; ++rq) {
            const ulonglong2 xv = *(const ulonglong2*)(xrow + 4 * rq);
            const int p = 2 * rq;
            #pragma unroll
            for (int g = 0; g < 4; ++g) {
                acc1[g][p]   = fma2(wipj[g], xv.x, b1pj[g]);
                acc1[g][p+1] = fma2(wipj[g], xv.y, b1pj[g]);
            }
        }
        const ull xv = *(const ull*)(xrow + 12);
        #pragma unroll
        for (int g = 0; g < 4; ++g) acc1[g][6] = fma2(wipj[g], xv, b1pj[g]);
    }

    #pragma unroll 1
    for (int t = 0; t < TT; ++t) {
        const int cur = t & 1, nxt = cur ^ 1;
        float* h1n = h1s + nxt * (HH * HSTR);
        float* h2c = h2s + cur * (HH * HSTR);
        float* h2n = h2s + nxt * (HH * HSTR);

        // ==== P1: gemm whh2*h2(t-1) -> acc2, fused with act1 + proj(t-1) ====
        #pragma unroll
        for (int p = 0; p < NRP; ++p) {
            acc2[0][p] = b2pj[0]; acc2[1][p] = b2pj[1];
            acc2[2][p] = b2pj[2]; acc2[3][p] = b2pj[3];
        }
        {
            float4 wv[4];
            #pragma unroll
            for (int i = 0; i < 4; ++i) wv[i] = __ldg(wt3 + i * HH);
            float* h1dst = h1n + j * HSTR;
            #pragma unroll
            for (int k4 = 0; k4 < 8; ++k4) {
                gemm_k4(acc2, wt3, h2c, k4, wv);
                if (k4 < NRP) ACT_PAIR(acc1, c1r, h1dst, k4);
            }
            float a0 = b1s[oo_out];
            #pragma unroll 1
            for (int k4 = 8; k4 < 32; ++k4) {
                gemm_k4(acc2, wt3, h2c, k4, wv);
                if (k4 < 24) {
                    const int kk0 = (k4 - 8) * 8;
                    #pragma unroll
                    for (int q = 0; q < 8; ++q)
                        a0 = fmaf(h2c[(kk0 + q) * HSTR + rr_out],
                                  W1s[(kk0 + q) * NOUT + oo_out], a0);
                }
            }
            if (t && wout)
                out[OUTS_BASE + ((size_t)(r0 + rr_out) * TT + (t - 1)) * NOUT + oo_out] = a0;
        }
        __syncthreads();   // bar1: h1(t) visible

        // ==== P2: gemm wih2*h1(t) -> acc2 ====
        {
            float4 wv[4];
            #pragma unroll
            for (int i = 0; i < 4; ++i) wv[i] = __ldg(wt2 + i * HH);
            #pragma unroll 1
            for (int k4 = 0; k4 < 32; ++k4)
                gemm_k4(acc2, wt2, h1n, k4, wv);
        }

        // ---- stage next x tile (uniform condition across the block) ----
        if (((t + 1) & 63) == 0 && (t + 1) < TT) {
            for (int idx = tid; idx < BR * 64; idx += NTHR) {
                const int rr = idx / 64, tt2 = idx % 64;
                const int gr = r0 + rr;
                xs[tt2 * HSTR + rr] =
                    x[(size_t)(gr < BB ? gr : BB - 1) * TT + (t + 1) + tt2];
            }
            __syncthreads();
        }

        // ==== P3: gemm whh1*h1(t) (+x(t+1)) -> acc1, fused with act2 ====
        {
            const float* xrow = xs + ((t + 1) & 63) * HSTR;
            #pragma unroll
            for (int rq = 0; rq < 3; ++rq) {
                const ulonglong2 xv = *(const ulonglong2*)(xrow + 4 * rq);
                const int p = 2 * rq;
                #pragma unroll
                for (int g = 0; g < 4; ++g) {
                    acc1[g][p]   = fma2(wipj[g], xv.x, b1pj[g]);
                    acc1[g][p+1] = fma2(wipj[g], xv.y, b1pj[g]);
                }
            }
            const ull xv = *(const ull*)(xrow + 12);
            #pragma unroll
            for (int g = 0; g < 4; ++g) acc1[g][6] = fma2(wipj[g], xv, b1pj[g]);

            float4 wv[4];
            #pragma unroll
            for (int i = 0; i < 4; ++i) wv[i] = __ldg(wt1 + i * HH);
            float* h2dst = h2n + j * HSTR;
            #pragma unroll
            for (int k4 = 0; k4 < 8; ++k4) {
                gemm_k4(acc1, wt1, h1n, k4, wv);
                if (k4 < NRP) ACT_PAIR(acc2, c2r, h2dst, k4);
            }
            #pragma unroll 1
            for (int k4 = 8; k4 < 32; ++k4)
                gemm_k4(acc1, wt1, h1n, k4, wv);
        }
        __syncthreads();   // bar2: h2(t) visible
    }

    // ---- epilogue: proj(TT-1) + output_cyto from final h2 (buffer 0, TT even) ----
    if (wout) {
        const float* hf = h2s;
        float a0 = b1s[oo_out];
        float a1 = b2s[oo_out];
        #pragma unroll 8
        for (int k = 0; k < HH; ++k) {
            const float hv = hf[k * HSTR + rr_out];
            a0 = fmaf(hv, W1s[k * NOUT + oo_out], a0);
            a1 = fmaf(hv, W2s[k * NOUT + oo_out], a1);
        }
        out[OUTS_BASE + ((size_t)(r0 + rr_out) * TT + (TT - 1)) * NOUT + oo_out] = a0;
        out[(size_t)(r0 + rr_out) * NOUT + oo_out] = a1;
    }
}

extern "C" void kernel_launch(void* const* d_in, const int* in_sizes, int n_in,
                              void* d_out, int out_size)
{
    (void)n_in; (void)out_size;
    const int o = (n_in >= 2 && in_sizes[1] == 1) ? 2 : 1;

    const float* x    = (const float*)d_in[0];
    const float* wih1 = (const float*)d_in[o + 0];
    const float* whh1 = (const float*)d_in[o + 1];
    const float* bih1 = (const float*)d_in[o + 2];
    const float* bhh1 = (const float*)d_in[o + 3];
    const float* wih2 = (const float*)d_in[o + 4];
    const float* whh2 = (const float*)d_in[o + 5];
    const float* bih2 = (const float*)d_in[o + 6];
    const float* bhh2 = (const float*)d_in[o + 7];
    const float* W1   = (const float*)d_in[o + 8];
    const float* b1   = (const float*)d_in[o + 9];
    const float* W2   = (const float*)d_in[o + 10];
    const float* b2   = (const float*)d_in[o + 11];

    // 1) transpose weights into __device__ scratch (k-major, gates packed)
    prep_w_kernel<<<(HH * HH + 255) / 256, 256>>>(whh1, wih2, whh2);

    // 2) main persistent recurrence kernel: 296 CTAs, 2 per SM, 128 threads each
    const size_t smem = (size_t)SM_TOT * sizeof(float);   // ~65 KB per CTA
    cudaFuncSetAttribute(lstm_kernel,
                         cudaFuncAttributeMaxDynamicSharedMemorySize, (int)smem);
    lstm_kernel<<<NCTA, NTHR, smem>>>(x, wih1, bih1, bhh1, bih2, bhh2,
                                      W1, b1, W2, b2, (float*)d_out);
}

// round 12
// speedup vs baseline: 1.0044x; 1.0044x over previous
#include <cuda_runtime.h>
#include <cstdint>

// Problem constants
#define BB   4096
#define TT   2048
#define HH   128
#define BR   28            // batch rows per CTA (148 x 28 = 4144 >= 4096, tail padded)
#define NCTA 148           // one CTA per SM
#define NTHR 256           // 8 warps -> 2 per SMSP
#define NOUT 8
#define HSTR 36            // smem row stride (floats): 144B, 16B-aligned (LDS.128-safe)

typedef unsigned long long ull;

// Non-aligned block barrier (used only for rare x-staging; uniform condition)
#define BARSYNC() asm volatile("barrier.sync 0;" ::: "memory")

// ---------- mbarrier helpers (split-phase producer/consumer sync) ----------
__device__ __forceinline__ uint32_t smem_u32(const void* p) {
    uint32_t a;
    asm("{ .reg .u64 t; cvta.to.shared.u64 t, %1; cvt.u32.u64 %0, t; }" : "=r"(a) : "l"(p));
    return a;
}
#define MBAR_INIT(addr, cnt) \
    asm volatile("mbarrier.init.shared.b64 [%0], %1;" :: "r"(addr), "r"(cnt) : "memory")
#define MBAR_ARRIVE(addr) \
    asm volatile("mbarrier.arrive.shared.b64 _, [%0];" :: "r"(addr) : "memory")
__device__ __forceinline__ void mbar_wait(uint32_t addr, uint32_t phase) {
    uint32_t done;
    asm volatile(
        "{\n\t.reg .pred p;\n\t"
        "mbarrier.try_wait.parity.acquire.cta.shared::cta.b64 p, [%1], %2;\n\t"
        "selp.b32 %0, 1, 0, p;\n\t}"
        : "=r"(done) : "r"(addr), "r"(phase) : "memory");
    while (!done) {
        asm volatile(
            "{\n\t.reg .pred p;\n\t"
            "mbarrier.try_wait.parity.acquire.cta.shared::cta.b64 p, [%1], %2, 0x989680;\n\t"
            "selp.b32 %0, 1, 0, p;\n\t}"
            : "=r"(done) : "r"(addr), "r"(phase) : "memory");
    }
}

// ---------- packed fp32x2 helpers ----------
__device__ __forceinline__ ull pack2(float a, float b) {
    ull r; asm("mov.b64 %0,{%1,%2};" : "=l"(r) : "f"(a), "f"(b)); return r;
}
__device__ __forceinline__ void unpack2(ull p, float& a, float& b) {
    asm("mov.b64 {%0,%1},%2;" : "=f"(a), "=f"(b) : "l"(p));
}
__device__ __forceinline__ ull fma2(ull a, ull b, ull c) {
    ull d; asm("fma.rn.f32x2 %0,%1,%2,%3;" : "=l"(d) : "l"(a), "l"(b), "l"(c)); return d;
}

// ---------- HW tanh activations (MUFU.TANH) ----------
__device__ __forceinline__ float tanha(float x) {
    float r; asm("tanh.approx.f32 %0,%1;" : "=f"(r) : "f"(x)); return r;
}
__device__ __forceinline__ float sigf(float x) {
    return fmaf(0.5f, tanha(0.5f * x), 0.5f);
}

// Transposed weights: [mat][k*128 + j] = float4 (g0,g1,g2,g3) for unit j, col k.
__device__ float4 g_wt[3][HH * HH];

__global__ void prep_w_kernel(const float* __restrict__ whh1,
                              const float* __restrict__ wih2,
                              const float* __restrict__ whh2)
{
    const int idx = blockIdx.x * blockDim.x + threadIdx.x;
    if (idx >= HH * HH) return;
    const int k = idx >> 7, j = idx & 127;
    const float* Ws[3] = { whh1, wih2, whh2 };
    #pragma unroll
    for (int m = 0; m < 3; ++m) {
        const float* W = Ws[m];
        g_wt[m][idx] = make_float4(W[(0 * HH + j) * HH + k],
                                   W[(1 * HH + j) * HH + k],
                                   W[(2 * HH + j) * HH + k],
                                   W[(3 * HH + j) * HH + k]);
    }
}

// One k4-group of the GEMM slice; NRQ = number of row quads this thread owns (4 or 3).
template<int NRQ>
__device__ __forceinline__ void gemm_k4(ull (&acc)[4][8],
                                        const float4* __restrict__ wt,
                                        const float* __restrict__ hbuf,   // h + rbase
                                        int k4, float4 (&wv)[4])
{
    float4 wn[4];
    const int kb = (k4 < 31) ? (k4 + 1) * 4 : 124;
    #pragma unroll
    for (int i = 0; i < 4; ++i) wn[i] = __ldg(wt + (kb + i) * HH);
    const float* hk = hbuf + (k4 * 4) * HSTR;
    #pragma unroll
    for (int kk = 0; kk < 4; ++kk) {
        const ull wp0 = pack2(wv[kk].x, wv[kk].x);
        const ull wp1 = pack2(wv[kk].y, wv[kk].y);
        const ull wp2 = pack2(wv[kk].z, wv[kk].z);
        const ull wp3 = pack2(wv[kk].w, wv[kk].w);
        const float* hkk = hk + kk * HSTR;
        #pragma unroll
        for (int rq = 0; rq < NRQ; ++rq) {
            const float4 h4 = *(const float4*)(hkk + 4 * rq);
            const ull hp0 = pack2(h4.x, h4.y);
            const ull hp1 = pack2(h4.z, h4.w);
            const int rp = 2 * rq;
            acc[0][rp]   = fma2(wp0, hp0, acc[0][rp]);
            acc[1][rp]   = fma2(wp1, hp0, acc[1][rp]);
            acc[2][rp]   = fma2(wp2, hp0, acc[2][rp]);
            acc[3][rp]   = fma2(wp3, hp0, acc[3][rp]);
            acc[0][rp+1] = fma2(wp0, hp1, acc[0][rp+1]);
            acc[1][rp+1] = fma2(wp1, hp1, acc[1][rp+1]);
            acc[2][rp+1] = fma2(wp2, hp1, acc[2][rp+1]);
            acc[3][rp+1] = fma2(wp3, hp1, acc[3][rp+1]);
        }
    }
    #pragma unroll
    for (int i = 0; i < 4; ++i) wv[i] = wn[i];
}

// One row-pair of activations (gates -> c,h), static pair index P.
#define ACT_PAIR(accX, cX, hdst, P) do {                                     \
    float iv0, iv1, fv0, fv1, gv0, gv1, ov0, ov1;                            \
    unpack2(accX[0][P], iv0, iv1);                                           \
    unpack2(accX[1][P], fv0, fv1);                                           \
    unpack2(accX[2][P], gv0, gv1);                                           \
    unpack2(accX[3][P], ov0, ov1);                                           \
    {   const float cn = sigf(fv0) * cX[2*(P)] + sigf(iv0) * tanha(gv0);     \
        cX[2*(P)] = cn;                                                      \
        (hdst)[2*(P)] = sigf(ov0) * tanha(cn); }                             \
    {   const float cn = sigf(fv1) * cX[2*(P)+1] + sigf(iv1) * tanha(gv1);   \
        cX[2*(P)+1] = cn;                                                    \
        (hdst)[2*(P)+1] = sigf(ov1) * tanha(cn); }                           \
} while (0)

// Dynamic smem layout (floats)
#define SM_H1  0                          // [2][128][HSTR]
#define SM_H2  (SM_H1 + 2 * HH * HSTR)    // [2][128][HSTR]
#define SM_XS  (SM_H2 + 2 * HH * HSTR)    // [64][HSTR]
#define SM_W1  (SM_XS + 64 * HSTR)        // [128][8] transposed [k][oo]
#define SM_W2  (SM_W1 + NOUT * HH)        // [128][8]
#define SM_B1  (SM_W2 + NOUT * HH)        // [8]
#define SM_B2  (SM_B1 + NOUT)             // [8]
#define SM_SB1 (SM_B2 + NOUT)             // [128][8] packed (bb1,bb1) per gate, per j
#define SM_SB2 (SM_SB1 + HH * 8)          // [128][8] packed (bb2,bb2)
#define SM_SWI (SM_SB2 + HH * 8)          // [128][8] packed (wi,wi)
#define SM_MB  (SM_SWI + HH * 8)          // 2 mbarriers (2 x 8B; offset 8B-aligned)
#define SM_TOT (SM_MB + 4)                // ~103.7 KB

// The full recurrence loop, templated on this warp-group's quad count.
// rh=0 warps: NRQ=4 (rows 0..15); rh=1 warps: NRQ=3 (rows 16..27).
// Sync: split-phase mbarriers. h1 barrier (mb1): arrive after P1's first 8
// k4-groups (all h1 writes done), wait just before P2. h2 barrier (mb2):
// arrive after P3's first 8 groups, wait at step end. 24 k4-groups of
// independent work sit inside each arrive->wait window, absorbing skew.
template<int NRQ>
__device__ __forceinline__ void run_steps(
    float* __restrict__ h1s, float* __restrict__ h2s, float* __restrict__ xs,
    const float* __restrict__ W1s, const float* __restrict__ b1s,
    const ull* __restrict__ b1pj, const ull* __restrict__ b2pj,
    const ull* __restrict__ wipj,
    const float4* __restrict__ wt1, const float4* __restrict__ wt2,
    const float4* __restrict__ wt3,
    const float* __restrict__ x, float* __restrict__ out,
    int j, int rbase, int r0, int rr_out, int oo_out, int tid,
    uint32_t mb1, uint32_t mb2)
{
    float c1r[2 * NRQ * 2], c2r[2 * NRQ * 2];
    #pragma unroll
    for (int i = 0; i < 4 * NRQ; ++i) { c1r[i] = 0.0f; c2r[i] = 0.0f; }

    ull acc1[4][8], acc2[4][8];
    const bool wout = (rr_out < BR) && (r0 + rr_out < BB);
    const size_t OUTS_BASE = (size_t)BB * NOUT;
    uint32_t ph1 = 0, ph2 = 0;

    // ---- prologue: acc1 = b1 + wi*x(0)  (h1(-1)=0) ----
    {
        const float* xrow = xs + rbase;
        #pragma unroll
        for (int rq = 0; rq < NRQ; ++rq) {
            const ulonglong2 xv = *(const ulonglong2*)(xrow + 4 * rq);
            const int rp = 2 * rq;
            #pragma unroll
            for (int g = 0; g < 4; ++g) {
                acc1[g][rp]   = fma2(wipj[g], xv.x, b1pj[g]);
                acc1[g][rp+1] = fma2(wipj[g], xv.y, b1pj[g]);
            }
        }
    }

    #pragma unroll 1
    for (int t = 0; t < TT; ++t) {
        const int cur = t & 1, nxt = cur ^ 1;
        float* h1n = h1s + nxt * (HH * HSTR);
        float* h2c = h2s + cur * (HH * HSTR);
        float* h2n = h2s + nxt * (HH * HSTR);
        const float* hb1 = h1n + rbase;
        const float* hb2 = h2c + rbase;

        // ==== P1: gemm whh2*h2(t-1) -> acc2, fused with act1 + proj(t-1) ====
        #pragma unroll
        for (int rp = 0; rp < 2 * NRQ; ++rp) {
            acc2[0][rp] = b2pj[0]; acc2[1][rp] = b2pj[1];
            acc2[2][rp] = b2pj[2]; acc2[3][rp] = b2pj[3];
        }
        {
            float4 wv[4];
            #pragma unroll
            for (int i = 0; i < 4; ++i) wv[i] = __ldg(wt3 + i * HH);
            float* h1dst = h1n + j * HSTR + rbase;
            #pragma unroll
            for (int k4 = 0; k4 < 8; ++k4) {
                gemm_k4<NRQ>(acc2, wt3, hb2, k4, wv);
                if (k4 < 2 * NRQ) ACT_PAIR(acc1, c1r, h1dst, k4);
            }
            MBAR_ARRIVE(mb1);                      // h1(t) written; don't wait yet
            float a0 = b1s[oo_out];
            #pragma unroll 1
            for (int k4 = 8; k4 < 32; ++k4) {
                gemm_k4<NRQ>(acc2, wt3, hb2, k4, wv);
                if (k4 < 24) {
                    const int kk0 = (k4 - 8) * 8;
                    #pragma unroll
                    for (int q = 0; q < 8; ++q)
                        a0 = fmaf(h2c[(kk0 + q) * HSTR + rr_out],
                                  W1s[(kk0 + q) * NOUT + oo_out], a0);
                }
            }
            if (t && wout)
                out[OUTS_BASE + ((size_t)(r0 + rr_out) * TT + (t - 1)) * NOUT + oo_out] = a0;
        }
        mbar_wait(mb1, ph1); ph1 ^= 1;             // h1(t) visible to all

        // ==== P2: gemm wih2*h1(t) -> acc2 ====
        {
            float4 wv[4];
            #pragma unroll
            for (int i = 0; i < 4; ++i) wv[i] = __ldg(wt2 + i * HH);
            #pragma unroll 1
            for (int k4 = 0; k4 < 32; ++k4)
                gemm_k4<NRQ>(acc2, wt2, hb1, k4, wv);
        }

        // ---- stage next x tile (uniform condition across the block) ----
        if (((t + 1) & 63) == 0 && (t + 1) < TT) {
            for (int idx = tid; idx < BR * 64; idx += NTHR) {
                const int rr = idx >> 6, tt2 = idx & 63;
                const int gr = r0 + rr;
                xs[tt2 * HSTR + rr] =
                    x[(size_t)(gr < BB ? gr : BB - 1) * TT + (t + 1) + tt2];
            }
            BARSYNC();
        }

        // ==== P3: gemm whh1*h1(t) (+x(t+1)) -> acc1, fused with act2 ====
        {
            const float* xrow = xs + ((t + 1) & 63) * HSTR + rbase;
            #pragma unroll
            for (int rq = 0; rq < NRQ; ++rq) {
                const ulonglong2 xv = *(const ulonglong2*)(xrow + 4 * rq);
                const int rp = 2 * rq;
                #pragma unroll
                for (int g = 0; g < 4; ++g) {
                    acc1[g][rp]   = fma2(wipj[g], xv.x, b1pj[g]);
                    acc1[g][rp+1] = fma2(wipj[g], xv.y, b1pj[g]);
                }
            }
            float4 wv[4];
            #pragma unroll
            for (int i = 0; i < 4; ++i) wv[i] = __ldg(wt1 + i * HH);
            float* h2dst = h2n + j * HSTR + rbase;
            #pragma unroll
            for (int k4 = 0; k4 < 8; ++k4) {
                gemm_k4<NRQ>(acc1, wt1, hb1, k4, wv);
                if (k4 < 2 * NRQ) ACT_PAIR(acc2, c2r, h2dst, k4);
            }
            MBAR_ARRIVE(mb2);                      // h2(t) written; don't wait yet
            #pragma unroll 1
            for (int k4 = 8; k4 < 32; ++k4)
                gemm_k4<NRQ>(acc1, wt1, hb1, k4, wv);
        }
        mbar_wait(mb2, ph2); ph2 ^= 1;             // h2(t) visible to all
    }
}

__global__ void __launch_bounds__(NTHR, 1)
lstm_kernel(const float* __restrict__ x,
            const float* __restrict__ wih1,
            const float* __restrict__ bih1, const float* __restrict__ bhh1,
            const float* __restrict__ bih2, const float* __restrict__ bhh2,
            const float* __restrict__ W1, const float* __restrict__ b1,
            const float* __restrict__ W2, const float* __restrict__ b2,
            float* __restrict__ out)
{
    extern __shared__ float sm[];
    float* h1s = sm + SM_H1;
    float* h2s = sm + SM_H2;
    float* xs  = sm + SM_XS;
    float* W1s = sm + SM_W1;
    float* W2s = sm + SM_W2;
    float* b1s = sm + SM_B1;
    float* b2s = sm + SM_B2;
    float* sb1 = sm + SM_SB1;
    float* sb2 = sm + SM_SB2;
    float* swi = sm + SM_SWI;

    const int tid = threadIdx.x;
    const int j   = tid & 127;           // hidden unit owned by this thread
    const int rh  = tid >> 7;            // 0: rows 0..15 (4 quads); 1: rows 16..27 (3)
    const int r0  = blockIdx.x * BR;     // first batch row of this CTA

    const uint32_t mb_base = smem_u32(sm + SM_MB);
    if (tid == 0) { MBAR_INIT(mb_base, NTHR); MBAR_INIT(mb_base + 8, NTHR); }

    // ---- init smem ----
    for (int i = tid; i < 2 * HH * HSTR; i += NTHR) { h1s[i] = 0.0f; h2s[i] = 0.0f; }
    for (int i = tid; i < NOUT * HH;     i += NTHR) {
        const int oo = i / HH, k = i % HH;
        W1s[k * NOUT + oo] = W1[i];
        W2s[k * NOUT + oo] = W2[i];
    }
    if (tid < NOUT) { b1s[tid] = b1[tid]; b2s[tid] = b2[tid]; }
    if (tid < HH) {
        #pragma unroll
        for (int g = 0; g < 4; ++g) {
            const int row = g * HH + tid;
            const float bb1 = bih1[row] + bhh1[row];
            const float bb2 = bih2[row] + bhh2[row];
            const float wv  = wih1[row];           // W_ih1 is (512,1)
            sb1[tid * 8 + 2 * g] = bb1; sb1[tid * 8 + 2 * g + 1] = bb1;
            sb2[tid * 8 + 2 * g] = bb2; sb2[tid * 8 + 2 * g + 1] = bb2;
            swi[tid * 8 + 2 * g] = wv;  swi[tid * 8 + 2 * g + 1] = wv;
        }
    }
    // ---- stage x tile 0 (clamped rows for the padded tail CTA) ----
    for (int idx = tid; idx < BR * 64; idx += NTHR) {
        const int rr = idx >> 6, tt2 = idx & 63;
        const int gr = r0 + rr;
        xs[tt2 * HSTR + rr] = x[(size_t)(gr < BB ? gr : BB - 1) * TT + tt2];
    }

    const float4* wt1 = g_wt[0] + j;   // whh1
    const float4* wt2 = g_wt[1] + j;   // wih2
    const float4* wt3 = g_wt[2] + j;   // whh2
    const ull* b1pj = (const ull*)(sb1 + j * 8);
    const ull* b2pj = (const ull*)(sb2 + j * 8);
    const ull* wipj = (const ull*)(swi + j * 8);

    const int rr_out = tid >> 3;
    const int oo_out = tid & 7;

    BARSYNC();   // mbarrier init + smem staging visible

    if (rh == 0)
        run_steps<4>(h1s, h2s, xs, W1s, b1s, b1pj, b2pj, wipj,
                     wt1, wt2, wt3, x, out, j, 0,  r0, rr_out, oo_out, tid,
                     mb_base, mb_base + 8);
    else
        run_steps<3>(h1s, h2s, xs, W1s, b1s, b1pj, b2pj, wipj,
                     wt1, wt2, wt3, x, out, j, 16, r0, rr_out, oo_out, tid,
                     mb_base, mb_base + 8);

    // ---- epilogue: proj(TT-1) + output_cyto from final h2 (buffer 0, TT even) ----
    if ((rr_out < BR) && (r0 + rr_out < BB)) {
        const float* hf = h2s;
        float a0 = b1s[oo_out];
        float a1 = b2s[oo_out];
        #pragma unroll 8
        for (int k = 0; k < HH; ++k) {
            const float hv = hf[k * HSTR + rr_out];
            a0 = fmaf(hv, W1s[k * NOUT + oo_out], a0);
            a1 = fmaf(hv, W2s[k * NOUT + oo_out], a1);
        }
        out[(size_t)BB * NOUT + ((size_t)(r0 + rr_out) * TT + (TT - 1)) * NOUT + oo_out] = a0;
        out[(size_t)(r0 + rr_out) * NOUT + oo_out] = a1;
    }
}

extern "C" void kernel_launch(void* const* d_in, const int* in_sizes, int n_in,
                              void* d_out, int out_size)
{
    (void)n_in; (void)out_size;
    const int o = (n_in >= 2 && in_sizes[1] == 1) ? 2 : 1;

    const float* x    = (const float*)d_in[0];
    const float* wih1 = (const float*)d_in[o + 0];
    const float* whh1 = (const float*)d_in[o + 1];
    const float* bih1 = (const float*)d_in[o + 2];
    const float* bhh1 = (const float*)d_in[o + 3];
    const float* wih2 = (const float*)d_in[o + 4];
    const float* whh2 = (const float*)d_in[o + 5];
    const float* bih2 = (const float*)d_in[o + 6];
    const float* bhh2 = (const float*)d_in[o + 7];
    const float* W1   = (const float*)d_in[o + 8];
    const float* b1   = (const float*)d_in[o + 9];
    const float* W2   = (const float*)d_in[o + 10];
    const float* b2   = (const float*)d_in[o + 11];

    // 1) transpose weights into __device__ scratch (k-major, gates packed)
    prep_w_kernel<<<(HH * HH + 255) / 256, 256>>>(whh1, wih2, whh2);

    // 2) main persistent recurrence kernel: 148 CTAs, split-phase mbarrier sync
    const size_t smem = (size_t)SM_TOT * sizeof(float);   // ~104 KB
    cudaFuncSetAttribute(lstm_kernel,
                         cudaFuncAttributeMaxDynamicSharedMemorySize, (int)smem);
    lstm_kernel<<<NCTA, NTHR, smem>>>(x, wih1, bih1, bhh1, bih2, bhh2,
                                      W1, b1, W2, b2, (float*)d_out);
}

// round 13
// speedup vs baseline: 1.0157x; 1.0112x over previous
#include <cuda_runtime.h>
#include <cstdint>

// Problem constants
#define BB   4096
#define TT   2048
#define HH   128
#define KPADK 136          // 128 k rows + 2 pad k4-groups (zero-init) for prefetch
#define BR   28            // batch rows per CTA (148 x 28 = 4144 >= 4096, tail padded)
#define NCTA 148           // one CTA per SM
#define NTHR 256           // 8 warps -> 2 per SMSP
#define NOUT 8
#define HSTR 36            // smem row stride (floats): 144B, 16B-aligned (LDS.128-safe)

typedef unsigned long long ull;

// Non-aligned barrier: all 256 threads arrive (possibly via divergent template paths)
#define BARSYNC() asm volatile("barrier.sync 0;" ::: "memory")

// ---------- packed fp32x2 helpers ----------
__device__ __forceinline__ ull pack2(float a, float b) {
    ull r; asm("mov.b64 %0,{%1,%2};" : "=l"(r) : "f"(a), "f"(b)); return r;
}
__device__ __forceinline__ void unpack2(ull p, float& a, float& b) {
    asm("mov.b64 {%0,%1},%2;" : "=f"(a), "=f"(b) : "l"(p));
}
__device__ __forceinline__ ull fma2(ull a, ull b, ull c) {
    ull d; asm("fma.rn.f32x2 %0,%1,%2,%3;" : "=l"(d) : "l"(a), "l"(b), "l"(c)); return d;
}

// ---------- HW tanh activations (MUFU.TANH) ----------
__device__ __forceinline__ float tanha(float x) {
    float r; asm("tanh.approx.f32 %0,%1;" : "=f"(r) : "f"(x)); return r;
}
__device__ __forceinline__ float sigf(float x) {
    return fmaf(0.5f, tanha(0.5f * x), 0.5f);
}

// Transposed weights: [mat][k*128 + j] = float4 (g0,g1,g2,g3) for unit j, col k.
// k rows [128, 136) are zero padding (static zero-init) -> unconditional prefetch.
__device__ float4 g_wt[3][KPADK * HH];

__global__ void prep_w_kernel(const float* __restrict__ whh1,
                              const float* __restrict__ wih2,
                              const float* __restrict__ whh2)
{
    const int idx = blockIdx.x * blockDim.x + threadIdx.x;
    if (idx >= HH * HH) return;
    const int k = idx >> 7, j = idx & 127;
    const float* Ws[3] = { whh1, wih2, whh2 };
    #pragma unroll
    for (int m = 0; m < 3; ++m) {
        const float* W = Ws[m];
        g_wt[m][idx] = make_float4(W[(0 * HH + j) * HH + k],
                                   W[(1 * HH + j) * HH + k],
                                   W[(2 * HH + j) * HH + k],
                                   W[(3 * HH + j) * HH + k]);
    }
}

// One k4-group (4 k) of the GEMM slice. Consumes wv, then REFILLS wv in place
// with group (k4+2)'s weights (wpre): each wv[kk] is reloaded immediately after
// its packs read it -> no copy-MOVs, and the LDG sits ~2 k4-groups (>= L2
// latency) ahead of its use.
template<int NRQ>
__device__ __forceinline__ void gemm_half(ull (&acc)[4][8],
                                          const float4* __restrict__ wpre,  // wt + (k4+2)*4*HH
                                          const float* __restrict__ hk,     // hbuf + k4*4*HSTR
                                          float4 (&wv)[4])
{
    #pragma unroll
    for (int kk = 0; kk < 4; ++kk) {
        const ull wp0 = pack2(wv[kk].x, wv[kk].x);
        const ull wp1 = pack2(wv[kk].y, wv[kk].y);
        const ull wp2 = pack2(wv[kk].z, wv[kk].z);
        const ull wp3 = pack2(wv[kk].w, wv[kk].w);
        wv[kk] = __ldg(wpre + kk * HH);                 // refill for k4+2 (WAR)
        const float* hkk = hk + kk * HSTR;
        #pragma unroll
        for (int rq = 0; rq < NRQ; ++rq) {
            const float4 h4 = *(const float4*)(hkk + 4 * rq);
            const ull hp0 = pack2(h4.x, h4.y);
            const ull hp1 = pack2(h4.z, h4.w);
            const int rp = 2 * rq;
            acc[0][rp]   = fma2(wp0, hp0, acc[0][rp]);
            acc[1][rp]   = fma2(wp1, hp0, acc[1][rp]);
            acc[2][rp]   = fma2(wp2, hp0, acc[2][rp]);
            acc[3][rp]   = fma2(wp3, hp0, acc[3][rp]);
            acc[0][rp+1] = fma2(wp0, hp1, acc[0][rp+1]);
            acc[1][rp+1] = fma2(wp1, hp1, acc[1][rp+1]);
            acc[2][rp+1] = fma2(wp2, hp1, acc[2][rp+1]);
            acc[3][rp+1] = fma2(wp3, hp1, acc[3][rp+1]);
        }
    }
}

#define GEMM_INIT(wt, wvA, wvB) do {                                          \
    _Pragma("unroll")                                                         \
    for (int i = 0; i < 4; ++i) {                                             \
        wvA[i] = __ldg((wt) + i * HH);                                        \
        wvB[i] = __ldg((wt) + (4 + i) * HH);                                  \
    }                                                                         \
} while (0)

// One row-pair of activations (gates -> c,h), static pair index P.
#define ACT_PAIR(accX, cX, hdst, P) do {                                     \
    float iv0, iv1, fv0, fv1, gv0, gv1, ov0, ov1;                            \
    unpack2(accX[0][P], iv0, iv1);                                           \
    unpack2(accX[1][P], fv0, fv1);                                           \
    unpack2(accX[2][P], gv0, gv1);                                           \
    unpack2(accX[3][P], ov0, ov1);                                           \
    {   const float cn = sigf(fv0) * cX[2*(P)] + sigf(iv0) * tanha(gv0);     \
        cX[2*(P)] = cn;                                                      \
        (hdst)[2*(P)] = sigf(ov0) * tanha(cn); }                             \
    {   const float cn = sigf(fv1) * cX[2*(P)+1] + sigf(iv1) * tanha(gv1);   \
        cX[2*(P)+1] = cn;                                                    \
        (hdst)[2*(P)+1] = sigf(ov1) * tanha(cn); }                           \
} while (0)

// Dynamic smem layout (floats)
#define SM_H1  0                          // [2][128][HSTR]
#define SM_H2  (SM_H1 + 2 * HH * HSTR)    // [2][128][HSTR]
#define SM_XS  (SM_H2 + 2 * HH * HSTR)    // [64][HSTR]
#define SM_W1  (SM_XS + 64 * HSTR)        // [128][8] transposed [k][oo]
#define SM_W2  (SM_W1 + NOUT * HH)        // [128][8]
#define SM_B1  (SM_W2 + NOUT * HH)        // [8]
#define SM_B2  (SM_B1 + NOUT)             // [8]
#define SM_SB1 (SM_B2 + NOUT)             // [128][8] packed (bb1,bb1) per gate, per j
#define SM_SB2 (SM_SB1 + HH * 8)          // [128][8] packed (bb2,bb2)
#define SM_SWI (SM_SB2 + HH * 8)          // [128][8] packed (wi,wi)
#define SM_TOT (SM_SWI + HH * 8)          // ~103.6 KB

// The full recurrence loop, templated on this warp-group's quad count.
// rh=0 warps: NRQ=4 (rows 0..15); rh=1 warps: NRQ=3 (rows 16..27).
template<int NRQ>
__device__ __forceinline__ void run_steps(
    float* __restrict__ h1s, float* __restrict__ h2s, float* __restrict__ xs,
    const float* __restrict__ W1s, const float* __restrict__ b1s,
    const ull* __restrict__ b1pj, const ull* __restrict__ b2pj,
    const ull* __restrict__ wipj,
    const float4* __restrict__ wt1, const float4* __restrict__ wt2,
    const float4* __restrict__ wt3,
    const float* __restrict__ x, float* __restrict__ out,
    int j, int rbase, int r0, int rr_out, int oo_out, int tid)
{
    float c1r[2 * NRQ * 2], c2r[2 * NRQ * 2];
    #pragma unroll
    for (int i = 0; i < 4 * NRQ; ++i) { c1r[i] = 0.0f; c2r[i] = 0.0f; }

    ull acc1[4][8], acc2[4][8];
    float4 wvA[4], wvB[4];
    const bool wout = (rr_out < BR) && (r0 + rr_out < BB);
    const size_t OUTS_BASE = (size_t)BB * NOUT;

    // ---- prologue: acc1 = b1 + wi*x(0)  (h1(-1)=0) ----
    {
        const float* xrow = xs + rbase;
        #pragma unroll
        for (int rq = 0; rq < NRQ; ++rq) {
            const ulonglong2 xv = *(const ulonglong2*)(xrow + 4 * rq);
            const int rp = 2 * rq;
            #pragma unroll
            for (int g = 0; g < 4; ++g) {
                acc1[g][rp]   = fma2(wipj[g], xv.x, b1pj[g]);
                acc1[g][rp+1] = fma2(wipj[g], xv.y, b1pj[g]);
            }
        }
    }

    #pragma unroll 1
    for (int t = 0; t < TT; ++t) {
        const int cur = t & 1, nxt = cur ^ 1;
        float* h1n = h1s + nxt * (HH * HSTR);
        float* h2c = h2s + cur * (HH * HSTR);
        float* h2n = h2s + nxt * (HH * HSTR);
        const float* hb1 = h1n + rbase;
        const float* hb2 = h2c + rbase;

        // ==== P1: gemm whh2*h2(t-1) -> acc2, fused with act1 + proj(t-1) ====
        #pragma unroll
        for (int rp = 0; rp < 2 * NRQ; ++rp) {
            acc2[0][rp] = b2pj[0]; acc2[1][rp] = b2pj[1];
            acc2[2][rp] = b2pj[2]; acc2[3][rp] = b2pj[3];
        }
        {
            GEMM_INIT(wt3, wvA, wvB);
            float* h1dst = h1n + j * HSTR + rbase;
            #pragma unroll
            for (int m = 0; m < 4; ++m) {                 // k4 = 0..7, ACT fused
                gemm_half<NRQ>(acc2, wt3 + (8*m+8)*HH,  hb2 + (8*m)*HSTR,   wvA);
                if (2*m     < 2*NRQ) ACT_PAIR(acc1, c1r, h1dst, 2*m);
                gemm_half<NRQ>(acc2, wt3 + (8*m+12)*HH, hb2 + (8*m+4)*HSTR, wvB);
                if (2*m + 1 < 2*NRQ) ACT_PAIR(acc1, c1r, h1dst, 2*m + 1);
            }
            float a0 = b1s[oo_out];
            #pragma unroll 1
            for (int m = 4; m < 16; ++m) {                // k4 = 8..31, proj fused
                gemm_half<NRQ>(acc2, wt3 + (8*m+8)*HH,  hb2 + (8*m)*HSTR,   wvA);
                if (m < 12) {
                    const int kk0 = (2*m - 8) * 8;
                    #pragma unroll
                    for (int q = 0; q < 8; ++q)
                        a0 = fmaf(h2c[(kk0 + q) * HSTR + rr_out],
                                  W1s[(kk0 + q) * NOUT + oo_out], a0);
                }
                gemm_half<NRQ>(acc2, wt3 + (8*m+12)*HH, hb2 + (8*m+4)*HSTR, wvB);
                if (m < 12) {
                    const int kk0 = (2*m - 7) * 8;
                    #pragma unroll
                    for (int q = 0; q < 8; ++q)
                        a0 = fmaf(h2c[(kk0 + q) * HSTR + rr_out],
                                  W1s[(kk0 + q) * NOUT + oo_out], a0);
                }
            }
            if (t && wout)
                out[OUTS_BASE + ((size_t)(r0 + rr_out) * TT + (t - 1)) * NOUT + oo_out] = a0;
        }
        BARSYNC();   // bar1: h1(t) visible

        // ==== P2: gemm wih2*h1(t) -> acc2 ====
        {
            GEMM_INIT(wt2, wvA, wvB);
            #pragma unroll 1
            for (int m = 0; m < 16; ++m) {
                gemm_half<NRQ>(acc2, wt2 + (8*m+8)*HH,  hb1 + (8*m)*HSTR,   wvA);
                gemm_half<NRQ>(acc2, wt2 + (8*m+12)*HH, hb1 + (8*m+4)*HSTR, wvB);
            }
        }

        // ---- stage next x tile (uniform condition across the block) ----
        if (((t + 1) & 63) == 0 && (t + 1) < TT) {
            for (int idx = tid; idx < BR * 64; idx += NTHR) {
                const int rr = idx >> 6, tt2 = idx & 63;
                const int gr = r0 + rr;
                xs[tt2 * HSTR + rr] =
                    x[(size_t)(gr < BB ? gr : BB - 1) * TT + (t + 1) + tt2];
            }
            BARSYNC();
        }

        // ==== P3: gemm whh1*h1(t) (+x(t+1)) -> acc1, fused with act2 ====
        {
            const float* xrow = xs + ((t + 1) & 63) * HSTR + rbase;
            #pragma unroll
            for (int rq = 0; rq < NRQ; ++rq) {
                const ulonglong2 xv = *(const ulonglong2*)(xrow + 4 * rq);
                const int rp = 2 * rq;
                #pragma unroll
                for (int g = 0; g < 4; ++g) {
                    acc1[g][rp]   = fma2(wipj[g], xv.x, b1pj[g]);
                    acc1[g][rp+1] = fma2(wipj[g], xv.y, b1pj[g]);
                }
            }
            GEMM_INIT(wt1, wvA, wvB);
            float* h2dst = h2n + j * HSTR + rbase;
            #pragma unroll
            for (int m = 0; m < 4; ++m) {                 // k4 = 0..7, ACT fused
                gemm_half<NRQ>(acc1, wt1 + (8*m+8)*HH,  hb1 + (8*m)*HSTR,   wvA);
                if (2*m     < 2*NRQ) ACT_PAIR(acc2, c2r, h2dst, 2*m);
                gemm_half<NRQ>(acc1, wt1 + (8*m+12)*HH, hb1 + (8*m+4)*HSTR, wvB);
                if (2*m + 1 < 2*NRQ) ACT_PAIR(acc2, c2r, h2dst, 2*m + 1);
            }
            #pragma unroll 1
            for (int m = 4; m < 16; ++m) {
                gemm_half<NRQ>(acc1, wt1 + (8*m+8)*HH,  hb1 + (8*m)*HSTR,   wvA);
                gemm_half<NRQ>(acc1, wt1 + (8*m+12)*HH, hb1 + (8*m+4)*HSTR, wvB);
            }
        }
        BARSYNC();   // bar2: h2(t) visible
    }
}

__global__ void __launch_bounds__(NTHR, 1)
lstm_kernel(const float* __restrict__ x,
            const float* __restrict__ wih1,
            const float* __restrict__ bih1, const float* __restrict__ bhh1,
            const float* __restrict__ bih2, const float* __restrict__ bhh2,
            const float* __restrict__ W1, const float* __restrict__ b1,
            const float* __restrict__ W2, const float* __restrict__ b2,
            float* __restrict__ out)
{
    extern __shared__ float sm[];
    float* h1s = sm + SM_H1;
    float* h2s = sm + SM_H2;
    float* xs  = sm + SM_XS;
    float* W1s = sm + SM_W1;
    float* W2s = sm + SM_W2;
    float* b1s = sm + SM_B1;
    float* b2s = sm + SM_B2;
    float* sb1 = sm + SM_SB1;
    float* sb2 = sm + SM_SB2;
    float* swi = sm + SM_SWI;

    const int tid = threadIdx.x;
    const int j   = tid & 127;           // hidden unit owned by this thread
    const int rh  = tid >> 7;            // 0: rows 0..15 (4 quads); 1: rows 16..27 (3)
    const int r0  = blockIdx.x * BR;     // first batch row of this CTA

    // ---- init smem ----
    for (int i = tid; i < 2 * HH * HSTR; i += NTHR) { h1s[i] = 0.0f; h2s[i] = 0.0f; }
    for (int i = tid; i < NOUT * HH;     i += NTHR) {
        const int oo = i / HH, k = i % HH;
        W1s[k * NOUT + oo] = W1[i];
        W2s[k * NOUT + oo] = W2[i];
    }
    if (tid < NOUT) { b1s[tid] = b1[tid]; b2s[tid] = b2[tid]; }
    if (tid < HH) {
        #pragma unroll
        for (int g = 0; g < 4; ++g) {
            const int row = g * HH + tid;
            const float bb1 = bih1[row] + bhh1[row];
            const float bb2 = bih2[row] + bhh2[row];
            const float wv  = wih1[row];           // W_ih1 is (512,1)
            sb1[tid * 8 + 2 * g] = bb1; sb1[tid * 8 + 2 * g + 1] = bb1;
            sb2[tid * 8 + 2 * g] = bb2; sb2[tid * 8 + 2 * g + 1] = bb2;
            swi[tid * 8 + 2 * g] = wv;  swi[tid * 8 + 2 * g + 1] = wv;
        }
    }
    // ---- stage x tile 0 (clamped rows for the padded tail CTA) ----
    for (int idx = tid; idx < BR * 64; idx += NTHR) {
        const int rr = idx >> 6, tt2 = idx & 63;
        const int gr = r0 + rr;
        xs[tt2 * HSTR + rr] = x[(size_t)(gr < BB ? gr : BB - 1) * TT + tt2];
    }

    const float4* wt1 = g_wt[0] + j;   // whh1
    const float4* wt2 = g_wt[1] + j;   // wih2
    const float4* wt3 = g_wt[2] + j;   // whh2
    const ull* b1pj = (const ull*)(sb1 + j * 8);
    const ull* b2pj = (const ull*)(sb2 + j * 8);
    const ull* wipj = (const ull*)(swi + j * 8);

    const int rr_out = tid >> 3;
    const int oo_out = tid & 7;

    BARSYNC();

    if (rh == 0)
        run_steps<4>(h1s, h2s, xs, W1s, b1s, b1pj, b2pj, wipj,
                     wt1, wt2, wt3, x, out, j, 0,  r0, rr_out, oo_out, tid);
    else
        run_steps<3>(h1s, h2s, xs, W1s, b1s, b1pj, b2pj, wipj,
                     wt1, wt2, wt3, x, out, j, 16, r0, rr_out, oo_out, tid);

    // ---- epilogue: proj(TT-1) + output_cyto from final h2 (buffer 0, TT even) ----
    if ((rr_out < BR) && (r0 + rr_out < BB)) {
        const float* hf = h2s;
        float a0 = b1s[oo_out];
        float a1 = b2s[oo_out];
        #pragma unroll 8
        for (int k = 0; k < HH; ++k) {
            const float hv = hf[k * HSTR + rr_out];
            a0 = fmaf(hv, W1s[k * NOUT + oo_out], a0);
            a1 = fmaf(hv, W2s[k * NOUT + oo_out], a1);
        }
        out[(size_t)BB * NOUT + ((size_t)(r0 + rr_out) * TT + (TT - 1)) * NOUT + oo_out] = a0;
        out[(size_t)(r0 + rr_out) * NOUT + oo_out] = a1;
    }
}

extern "C" void kernel_launch(void* const* d_in, const int* in_sizes, int n_in,
                              void* d_out, int out_size)
{
    (void)n_in; (void)out_size;
    const int o = (n_in >= 2 && in_sizes[1] == 1) ? 2 : 1;

    const float* x    = (const float*)d_in[0];
    const float* wih1 = (const float*)d_in[o + 0];
    const float* whh1 = (const float*)d_in[o + 1];
    const float* bih1 = (const float*)d_in[o + 2];
    const float* bhh1 = (const float*)d_in[o + 3];
    const float* wih2 = (const float*)d_in[o + 4];
    const float* whh2 = (const float*)d_in[o + 5];
    const float* bih2 = (const float*)d_in[o + 6];
    const float* bhh2 = (const float*)d_in[o + 7];
    const float* W1   = (const float*)d_in[o + 8];
    const float* b1   = (const float*)d_in[o + 9];
    const float* W2   = (const float*)d_in[o + 10];
    const float* b2   = (const float*)d_in[o + 11];

    // 1) transpose weights into __device__ scratch (k-major, gates packed, k-padded)
    prep_w_kernel<<<(HH * HH + 255) / 256, 256>>>(whh1, wih2, whh2);

    // 2) main persistent recurrence kernel: 148 CTAs, depth-2 weight prefetch
    const size_t smem = (size_t)SM_TOT * sizeof(float);   // ~104 KB
    cudaFuncSetAttribute(lstm_kernel,
                         cudaFuncAttributeMaxDynamicSharedMemorySize, (int)smem);
    lstm_kernel<<<NCTA, NTHR, smem>>>(x, wih1, bih1, bhh1, bih2, bhh2,
                                      W1, b1, W2, b2, (float*)d_out);
}

// round 14
// speedup vs baseline: 1.0545x; 1.0382x over previous
#include <cuda_runtime.h>
#include <cstdint>

// Problem constants
#define BB   4096
#define TT   2048
#define HH   128
#define BR   28            // batch rows per CTA (148 x 28 = 4144 >= 4096, tail padded)
#define NCTA 148           // one CTA per SM
#define NTHR 256           // 8 warps -> 2 per SMSP
#define NOUT 8
#define HSTR 36            // smem row stride (floats): 144B, 16B-aligned (LDS.128-safe)

typedef unsigned long long ull;

// Non-aligned barrier: all 256 threads arrive (possibly via divergent template paths)
#define BARSYNC() asm volatile("barrier.sync 0;" ::: "memory")

// ---------- packed fp32x2 helpers ----------
__device__ __forceinline__ ull pack2(float a, float b) {
    ull r; asm("mov.b64 %0,{%1,%2};" : "=l"(r) : "f"(a), "f"(b)); return r;
}
__device__ __forceinline__ void unpack2(ull p, float& a, float& b) {
    asm("mov.b64 {%0,%1},%2;" : "=f"(a), "=f"(b) : "l"(p));
}
__device__ __forceinline__ ull fma2(ull a, ull b, ull c) {
    ull d; asm("fma.rn.f32x2 %0,%1,%2,%3;" : "=l"(d) : "l"(a), "l"(b), "l"(c)); return d;
}

// ---------- HW tanh activations (MUFU.TANH) ----------
__device__ __forceinline__ float tanha(float x) {
    float r; asm("tanh.approx.f32 %0,%1;" : "=f"(r) : "f"(x)); return r;
}
__device__ __forceinline__ float sigf(float x) {
    return fmaf(0.5f, tanha(0.5f * x), 0.5f);
}

// Transposed weights: [mat][k*128 + j] = float4 (g0,g1,g2,g3) for unit j, col k.
__device__ float4 g_wt[3][HH * HH];

__global__ void prep_w_kernel(const float* __restrict__ whh1,
                              const float* __restrict__ wih2,
                              const float* __restrict__ whh2)
{
    const int idx = blockIdx.x * blockDim.x + threadIdx.x;
    if (idx >= HH * HH) return;
    const int k = idx >> 7, j = idx & 127;
    const float* Ws[3] = { whh1, wih2, whh2 };
    #pragma unroll
    for (int m = 0; m < 3; ++m) {
        const float* W = Ws[m];
        g_wt[m][idx] = make_float4(W[(0 * HH + j) * HH + k],
                                   W[(1 * HH + j) * HH + k],
                                   W[(2 * HH + j) * HH + k],
                                   W[(3 * HH + j) * HH + k]);
    }
}

// One kk sub-step: prefetch h for the NEXT kk into `nxt`, then FMA with `cur`.
// The h load sits ~one kk (>= 20 issue cycles x 2 warps) ahead of its use,
// hiding the 29-cycle LDS latency that was previously fully exposed.
#define GK4_KK(kk, cur, nxt, hpnext) do {                                    \
    _Pragma("unroll")                                                        \
    for (int rq = 0; rq < NRQ; ++rq)                                         \
        nxt[rq] = *(const float4*)((hpnext) + 4 * rq);                       \
    const ull wp0 = pack2(wv[kk].x, wv[kk].x);                               \
    const ull wp1 = pack2(wv[kk].y, wv[kk].y);                               \
    const ull wp2 = pack2(wv[kk].z, wv[kk].z);                               \
    const ull wp3 = pack2(wv[kk].w, wv[kk].w);                               \
    _Pragma("unroll")                                                        \
    for (int rq = 0; rq < NRQ; ++rq) {                                       \
        const ull hp0 = pack2(cur[rq].x, cur[rq].y);                         \
        const ull hp1 = pack2(cur[rq].z, cur[rq].w);                         \
        const int rp = 2 * rq;                                               \
        acc[0][rp]   = fma2(wp0, hp0, acc[0][rp]);                           \
        acc[1][rp]   = fma2(wp1, hp0, acc[1][rp]);                           \
        acc[2][rp]   = fma2(wp2, hp0, acc[2][rp]);                           \
        acc[3][rp]   = fma2(wp3, hp0, acc[3][rp]);                           \
        acc[0][rp+1] = fma2(wp0, hp1, acc[0][rp+1]);                         \
        acc[1][rp+1] = fma2(wp1, hp1, acc[1][rp+1]);                         \
        acc[2][rp+1] = fma2(wp2, hp1, acc[2][rp+1]);                         \
        acc[3][rp+1] = fma2(wp3, hp1, acc[3][rp+1]);                         \
    }                                                                        \
} while (0)

// One k4-group. Weights prefetched one group ahead (wv), h quads pipelined one
// kk ahead via ha/hb ping-pong (ha holds kk=0 of this group at entry; on exit
// holds kk=0 of the next group).
template<int NRQ>
__device__ __forceinline__ void gemm_k4(ull (&acc)[4][8],
                                        const float4* __restrict__ wt,
                                        const float* __restrict__ hbuf,   // h + rbase
                                        int k4, float4 (&wv)[4],
                                        float4 (&ha)[4], float4 (&hb)[4])
{
    float4 wn[4];
    const int kb = (k4 < 31) ? (k4 + 1) * 4 : 124;
    #pragma unroll
    for (int i = 0; i < 4; ++i) wn[i] = __ldg(wt + (kb + i) * HH);
    const float* hk = hbuf + (k4 * 4) * HSTR;
    const float* hnx = hbuf + kb * HSTR;     // next group's kk=0 (clamped; redundant on last)
    GK4_KK(0, ha, hb, hk + 1 * HSTR);
    GK4_KK(1, hb, ha, hk + 2 * HSTR);
    GK4_KK(2, ha, hb, hk + 3 * HSTR);
    GK4_KK(3, hb, ha, hnx);                  // ha <- next group's kk=0
    #pragma unroll
    for (int i = 0; i < 4; ++i) wv[i] = wn[i];
}

#define GEMM_INIT(wt, hb0, wv, ha) do {                                      \
    _Pragma("unroll")                                                        \
    for (int i = 0; i < 4; ++i) wv[i] = __ldg((wt) + i * HH);                \
    _Pragma("unroll")                                                        \
    for (int rq = 0; rq < NRQ; ++rq)                                         \
        ha[rq] = *(const float4*)((hb0) + 4 * rq);                           \
} while (0)

// One row-pair of activations (gates -> c,h), static pair index P.
#define ACT_PAIR(accX, cX, hdst, P) do {                                     \
    float iv0, iv1, fv0, fv1, gv0, gv1, ov0, ov1;                            \
    unpack2(accX[0][P], iv0, iv1);                                           \
    unpack2(accX[1][P], fv0, fv1);                                           \
    unpack2(accX[2][P], gv0, gv1);                                           \
    unpack2(accX[3][P], ov0, ov1);                                           \
    {   const float cn = sigf(fv0) * cX[2*(P)] + sigf(iv0) * tanha(gv0);     \
        cX[2*(P)] = cn;                                                      \
        (hdst)[2*(P)] = sigf(ov0) * tanha(cn); }                             \
    {   const float cn = sigf(fv1) * cX[2*(P)+1] + sigf(iv1) * tanha(gv1);   \
        cX[2*(P)+1] = cn;                                                    \
        (hdst)[2*(P)+1] = sigf(ov1) * tanha(cn); }                           \
} while (0)

// Dynamic smem layout (floats)
#define SM_H1  0                          // [2][128][HSTR]
#define SM_H2  (SM_H1 + 2 * HH * HSTR)    // [2][128][HSTR]
#define SM_XS  (SM_H2 + 2 * HH * HSTR)    // [64][HSTR]
#define SM_W1  (SM_XS + 64 * HSTR)        // [128][8] transposed [k][oo]
#define SM_W2  (SM_W1 + NOUT * HH)        // [128][8]
#define SM_B1  (SM_W2 + NOUT * HH)        // [8]
#define SM_B2  (SM_B1 + NOUT)             // [8]
#define SM_SB1 (SM_B2 + NOUT)             // [128][8] packed (bb1,bb1) per gate, per j
#define SM_SB2 (SM_SB1 + HH * 8)          // [128][8] packed (bb2,bb2)
#define SM_SWI (SM_SB2 + HH * 8)          // [128][8] packed (wi,wi)
#define SM_TOT (SM_SWI + HH * 8)          // ~103.6 KB

// rh=0 warps: NRQ=4 (rows 0..15); rh=1 warps: NRQ=3 (rows 16..27).
template<int NRQ>
__device__ __forceinline__ void run_steps(
    float* __restrict__ h1s, float* __restrict__ h2s, float* __restrict__ xs,
    const float* __restrict__ W1s, const float* __restrict__ b1s,
    const ull* __restrict__ b1pj, const ull* __restrict__ b2pj,
    const ull* __restrict__ wipj,
    const float4* __restrict__ wt1, const float4* __restrict__ wt2,
    const float4* __restrict__ wt3,
    const float* __restrict__ x, float* __restrict__ out,
    int j, int rbase, int r0, int rr_out, int oo_out, int tid)
{
    float c1r[2 * NRQ * 2], c2r[2 * NRQ * 2];
    #pragma unroll
    for (int i = 0; i < 4 * NRQ; ++i) { c1r[i] = 0.0f; c2r[i] = 0.0f; }

    ull acc1[4][8], acc2[4][8];
    float4 wv[4], ha[4], hb[4];
    const bool wout = (rr_out < BR) && (r0 + rr_out < BB);
    const size_t OUTS_BASE = (size_t)BB * NOUT;

    // ---- prologue: acc1 = b1 + wi*x(0)  (h1(-1)=0) ----
    {
        const float* xrow = xs + rbase;
        #pragma unroll
        for (int rq = 0; rq < NRQ; ++rq) {
            const ulonglong2 xv = *(const ulonglong2*)(xrow + 4 * rq);
            const int rp = 2 * rq;
            #pragma unroll
            for (int g = 0; g < 4; ++g) {
                acc1[g][rp]   = fma2(wipj[g], xv.x, b1pj[g]);
                acc1[g][rp+1] = fma2(wipj[g], xv.y, b1pj[g]);
            }
        }
    }

    #pragma unroll 1
    for (int t = 0; t < TT; ++t) {
        const int cur = t & 1, nxt = cur ^ 1;
        float* h1n = h1s + nxt * (HH * HSTR);
        float* h2c = h2s + cur * (HH * HSTR);
        float* h2n = h2s + nxt * (HH * HSTR);
        const float* hb1 = h1n + rbase;
        const float* hb2 = h2c + rbase;

        // ==== P1: gemm whh2*h2(t-1) -> acc2, fused with act1 + proj(t-1) ====
        #pragma unroll
        for (int rp = 0; rp < 2 * NRQ; ++rp) {
            acc2[0][rp] = b2pj[0]; acc2[1][rp] = b2pj[1];
            acc2[2][rp] = b2pj[2]; acc2[3][rp] = b2pj[3];
        }
        {
            GEMM_INIT(wt3, hb2, wv, ha);
            float* h1dst = h1n + j * HSTR + rbase;
            #pragma unroll
            for (int k4 = 0; k4 < 8; ++k4) {
                gemm_k4<NRQ>(acc2, wt3, hb2, k4, wv, ha, hb);
                if (k4 < 2 * NRQ) ACT_PAIR(acc1, c1r, h1dst, k4);
            }
            float a0 = b1s[oo_out];
            #pragma unroll 1
            for (int k4 = 8; k4 < 32; ++k4) {
                gemm_k4<NRQ>(acc2, wt3, hb2, k4, wv, ha, hb);
                if (k4 < 24) {
                    const int kk0 = (k4 - 8) * 8;
                    #pragma unroll
                    for (int q = 0; q < 8; ++q)
                        a0 = fmaf(h2c[(kk0 + q) * HSTR + rr_out],
                                  W1s[(kk0 + q) * NOUT + oo_out], a0);
                }
            }
            if (t && wout)
                out[OUTS_BASE + ((size_t)(r0 + rr_out) * TT + (t - 1)) * NOUT + oo_out] = a0;
        }
        BARSYNC();   // bar1: h1(t) visible

        // ==== P2: gemm wih2*h1(t) -> acc2 ====
        {
            GEMM_INIT(wt2, hb1, wv, ha);
            #pragma unroll 1
            for (int k4 = 0; k4 < 32; ++k4)
                gemm_k4<NRQ>(acc2, wt2, hb1, k4, wv, ha, hb);
        }

        // ---- stage next x tile (uniform condition across the block) ----
        if (((t + 1) & 63) == 0 && (t + 1) < TT) {
            for (int idx = tid; idx < BR * 64; idx += NTHR) {
                const int rr = idx >> 6, tt2 = idx & 63;
                const int gr = r0 + rr;
                xs[tt2 * HSTR + rr] =
                    x[(size_t)(gr < BB ? gr : BB - 1) * TT + (t + 1) + tt2];
            }
            BARSYNC();
        }

        // ==== P3: gemm whh1*h1(t) (+x(t+1)) -> acc1, fused with act2 ====
        {
            const float* xrow = xs + ((t + 1) & 63) * HSTR + rbase;
            #pragma unroll
            for (int rq = 0; rq < NRQ; ++rq) {
                const ulonglong2 xv = *(const ulonglong2*)(xrow + 4 * rq);
                const int rp = 2 * rq;
                #pragma unroll
                for (int g = 0; g < 4; ++g) {
                    acc1[g][rp]   = fma2(wipj[g], xv.x, b1pj[g]);
                    acc1[g][rp+1] = fma2(wipj[g], xv.y, b1pj[g]);
                }
            }
            GEMM_INIT(wt1, hb1, wv, ha);
            float* h2dst = h2n + j * HSTR + rbase;
            #pragma unroll
            for (int k4 = 0; k4 < 8; ++k4) {
                gemm_k4<NRQ>(acc1, wt1, hb1, k4, wv, ha, hb);
                if (k4 < 2 * NRQ) ACT_PAIR(acc2, c2r, h2dst, k4);
            }
            #pragma unroll 1
            for (int k4 = 8; k4 < 32; ++k4)
                gemm_k4<NRQ>(acc1, wt1, hb1, k4, wv, ha, hb);
        }
        BARSYNC();   // bar2: h2(t) visible
    }
}

__global__ void __launch_bounds__(NTHR, 1)
lstm_kernel(const float* __restrict__ x,
            const float* __restrict__ wih1,
            const float* __restrict__ bih1, const float* __restrict__ bhh1,
            const float* __restrict__ bih2, const float* __restrict__ bhh2,
            const float* __restrict__ W1, const float* __restrict__ b1,
            const float* __restrict__ W2, const float* __restrict__ b2,
            float* __restrict__ out)
{
    extern __shared__ float sm[];
    float* h1s = sm + SM_H1;
    float* h2s = sm + SM_H2;
    float* xs  = sm + SM_XS;
    float* W1s = sm + SM_W1;
    float* W2s = sm + SM_W2;
    float* b1s = sm + SM_B1;
    float* b2s = sm + SM_B2;
    float* sb1 = sm + SM_SB1;
    float* sb2 = sm + SM_SB2;
    float* swi = sm + SM_SWI;

    const int tid = threadIdx.x;
    const int j   = tid & 127;           // hidden unit owned by this thread
    const int rh  = tid >> 7;            // 0: rows 0..15 (4 quads); 1: rows 16..27 (3)
    const int r0  = blockIdx.x * BR;     // first batch row of this CTA

    // ---- init smem ----
    for (int i = tid; i < 2 * HH * HSTR; i += NTHR) { h1s[i] = 0.0f; h2s[i] = 0.0f; }
    for (int i = tid; i < NOUT * HH;     i += NTHR) {
        const int oo = i / HH, k = i % HH;
        W1s[k * NOUT + oo] = W1[i];
        W2s[k * NOUT + oo] = W2[i];
    }
    if (tid < NOUT) { b1s[tid] = b1[tid]; b2s[tid] = b2[tid]; }
    if (tid < HH) {
        #pragma unroll
        for (int g = 0; g < 4; ++g) {
            const int row = g * HH + tid;
            const float bb1 = bih1[row] + bhh1[row];
            const float bb2 = bih2[row] + bhh2[row];
            const float wv  = wih1[row];           // W_ih1 is (512,1)
            sb1[tid * 8 + 2 * g] = bb1; sb1[tid * 8 + 2 * g + 1] = bb1;
            sb2[tid * 8 + 2 * g] = bb2; sb2[tid * 8 + 2 * g + 1] = bb2;
            swi[tid * 8 + 2 * g] = wv;  swi[tid * 8 + 2 * g + 1] = wv;
        }
    }
    // ---- stage x tile 0 (clamped rows for the padded tail CTA) ----
    for (int idx = tid; idx < BR * 64; idx += NTHR) {
        const int rr = idx >> 6, tt2 = idx & 63;
        const int gr = r0 + rr;
        xs[tt2 * HSTR + rr] = x[(size_t)(gr < BB ? gr : BB - 1) * TT + tt2];
    }

    const float4* wt1 = g_wt[0] + j;   // whh1
    const float4* wt2 = g_wt[1] + j;   // wih2
    const float4* wt3 = g_wt[2] + j;   // whh2
    const ull* b1pj = (const ull*)(sb1 + j * 8);
    const ull* b2pj = (const ull*)(sb2 + j * 8);
    const ull* wipj = (const ull*)(swi + j * 8);

    const int rr_out = tid >> 3;
    const int oo_out = tid & 7;

    BARSYNC();

    if (rh == 0)
        run_steps<4>(h1s, h2s, xs, W1s, b1s, b1pj, b2pj, wipj,
                     wt1, wt2, wt3, x, out, j, 0,  r0, rr_out, oo_out, tid);
    else
        run_steps<3>(h1s, h2s, xs, W1s, b1s, b1pj, b2pj, wipj,
                     wt1, wt2, wt3, x, out, j, 16, r0, rr_out, oo_out, tid);

    // ---- epilogue: proj(TT-1) + output_cyto from final h2 (buffer 0, TT even) ----
    if ((rr_out < BR) && (r0 + rr_out < BB)) {
        const float* hf = h2s;
        float a0 = b1s[oo_out];
        float a1 = b2s[oo_out];
        #pragma unroll 8
        for (int k = 0; k < HH; ++k) {
            const float hv = hf[k * HSTR + rr_out];
            a0 = fmaf(hv, W1s[k * NOUT + oo_out], a0);
            a1 = fmaf(hv, W2s[k * NOUT + oo_out], a1);
        }
        out[(size_t)BB * NOUT + ((size_t)(r0 + rr_out) * TT + (TT - 1)) * NOUT + oo_out] = a0;
        out[(size_t)(r0 + rr_out) * NOUT + oo_out] = a1;
    }
}

extern "C" void kernel_launch(void* const* d_in, const int* in_sizes, int n_in,
                              void* d_out, int out_size)
{
    (void)n_in; (void)out_size;
    const int o = (n_in >= 2 && in_sizes[1] == 1) ? 2 : 1;

    const float* x    = (const float*)d_in[0];
    const float* wih1 = (const float*)d_in[o + 0];
    const float* whh1 = (const float*)d_in[o + 1];
    const float* bih1 = (const float*)d_in[o + 2];
    const float* bhh1 = (const float*)d_in[o + 3];
    const float* wih2 = (const float*)d_in[o + 4];
    const float* whh2 = (const float*)d_in[o + 5];
    const float* bih2 = (const float*)d_in[o + 6];
    const float* bhh2 = (const float*)d_in[o + 7];
    const float* W1   = (const float*)d_in[o + 8];
    const float* b1   = (const float*)d_in[o + 9];
    const float* W2   = (const float*)d_in[o + 10];
    const float* b2   = (const float*)d_in[o + 11];

    // 1) transpose weights into __device__ scratch (k-major, gates packed)
    prep_w_kernel<<<(HH * HH + 255) / 256, 256>>>(whh1, wih2, whh2);

    // 2) main persistent recurrence kernel: 148 CTAs, h-operand software pipeline
    const size_t smem = (size_t)SM_TOT * sizeof(float);   // ~104 KB
    cudaFuncSetAttribute(lstm_kernel,
                         cudaFuncAttributeMaxDynamicSharedMemorySize, (int)smem);
    lstm_kernel<<<NCTA, NTHR, smem>>>(x, wih1, bih1, bhh1, bih2, bhh2,
                                      W1, b1, W2, b2, (float*)d_out);
}